// round 10
// baseline (speedup 1.0000x reference)
#include <cuda_runtime.h>
#include <stdint.h>

#define NQ      8
#define NPAIRS  28
#define NB      16384
#define THREADS 128

typedef unsigned long long u64;

// ---------------- f32x2 packed helpers ----------------
__device__ __forceinline__ u64 pk(float lo, float hi) {
    u64 v; asm("mov.b64 %0, {%1, %2};" : "=l"(v) : "f"(lo), "f"(hi)); return v;
}
__device__ __forceinline__ void upk(u64 v, float& lo, float& hi) {
    asm("mov.b64 {%0, %1}, %2;" : "=f"(lo), "=f"(hi) : "l"(v));
}
__device__ __forceinline__ u64 bc2(float x) { return pk(x, x); }
__device__ __forceinline__ u64 sw2(u64 v) {
    float lo, hi; upk(v, lo, hi); return pk(hi, lo);
}
__device__ __forceinline__ u64 fma2(u64 a, u64 b, u64 c) {
    u64 d; asm("fma.rn.f32x2 %0, %1, %2, %3;" : "=l"(d) : "l"(a), "l"(b), "l"(c)); return d;
}
__device__ __forceinline__ u64 mul2(u64 a, u64 b) {
    u64 d; asm("mul.rn.f32x2 %0, %1, %2;" : "=l"(d) : "l"(a), "l"(b)); return d;
}
__device__ __forceinline__ u64 shflx2(u64 v, int m) {
    float lo, hi; upk(v, lo, hi);
    lo = __shfl_xor_sync(0xffffffffu, lo, m);
    hi = __shfl_xor_sync(0xffffffffu, hi, m);
    return pk(lo, hi);
}

// ---------------- gate primitives ----------------
__device__ __forceinline__ void ry_lane_m(u64 (&a)[8], float c, float s,
                                          int mask, unsigned lam) {
    const u64 c2 = bc2(c);
    const u64 sg2 = bc2(lam ? s : -s);
#pragma unroll
    for (int r = 0; r < 8; r++) {
        u64 p = shflx2(a[r], mask);
        a[r] = fma2(sg2, p, mul2(c2, a[r]));
    }
}

__device__ __forceinline__ void ry_reg_m(u64 (&a)[8], float c, float s, int m) {
    const u64 c2 = bc2(c), s2 = bc2(s), ns2 = bc2(-s);
#pragma unroll
    for (int r = 0; r < 8; r++) {
        if (!(r & m)) {
            u64 x = a[r], y = a[r | m];
            a[r]     = fma2(ns2, y, mul2(c2, x));
            a[r | m] = fma2(s2,  x, mul2(c2, y));
        }
    }
}

__device__ __forceinline__ float lane_wht(float v, unsigned lane) {
#pragma unroll
    for (int m = 1; m < 32; m <<= 1) {
        float t = __shfl_xor_sync(0xffffffffu, v, m);
        v = (lane & m) ? (t - v) : (v + t);
    }
    return v;
}

// ---------------- single fused kernel ----------------

__global__ void __launch_bounds__(THREADS, 9)
vqc_kernel(const float4* __restrict__ theta4, const float4* __restrict__ phi4,
           const float4* __restrict__ jup4, const float* __restrict__ w,
           float* __restrict__ out) {
    // block-shared batch-independent tables
    __shared__ float2 s_cs[2 * NQ];      // cos/sin(theta_w/2) per (layer,qubit)
    __shared__ float2 s_hw[NQ];          // (0.5*phi_w(l0), 0.5*phi_w(l1))
    __shared__ u64    s_d2t[8][32];      // DIAG2 complex factor, transposed [r][lane]

    const unsigned t    = threadIdx.x;
    const unsigned tid  = blockIdx.x * THREADS + t;
    const unsigned b    = tid >> 5;
    const unsigned lane = tid & 31;

    // ---- cooperative table build ----
    if (t < 2 * NQ) {
        float c, s;
        __sincosf(0.5f * w[t * 3 + 1], &s, &c);
        s_cs[t] = make_float2(c, s);
    } else if (t < 3 * NQ) {
        int i = t - 2 * NQ;
        s_hw[i] = make_float2(0.5f * w[i * 3], 0.5f * w[(NQ + i) * 3]);
    }
    {
        int idx = (int)t * 2;            // even entry; odd differs only in r bit0
        int ln = idx >> 3, r0 = idx & 7;
        float h[8];
#pragma unroll
        for (int k = 0; k < 8; k++) h[k] = 0.5f * w[k * 3 + 2];
        float phr = 0.f;
#pragma unroll
        for (int k = 0; k < 5; k++)
            phr += ((ln >> (4 - k)) & 1) ? h[k] : -h[k];
        phr += ((r0 >> 2) & 1) ? h[5] : -h[5];
        phr += ((r0 >> 1) & 1) ? h[6] : -h[6];
        phr -= h[7];
        float ss, cc;
        __sincosf(phr, &ss, &cc);
        s_d2t[r0][ln] = pk(cc, ss);
        __sincosf(phr + 2.f * h[7], &ss, &cc);
        s_d2t[r0 + 1][ln] = pk(cc, ss);
    }
    __syncthreads();

    // ===== setup + init (all batch arrays transient; nothing lives past init) =====
    u64 a[8];
    {
        float th[NQ], phv[NQ], J[NPAIRS];
        {
            float4 t0 = theta4[b * 2], t1 = theta4[b * 2 + 1];
            th[0]=t0.x; th[1]=t0.y; th[2]=t0.z; th[3]=t0.w;
            th[4]=t1.x; th[5]=t1.y; th[6]=t1.z; th[7]=t1.w;
            float4 p0 = phi4[b * 2], p1 = phi4[b * 2 + 1];
            phv[0]=p0.x; phv[1]=p0.y; phv[2]=p0.z; phv[3]=p0.w;
            phv[4]=p1.x; phv[5]=p1.y; phv[6]=p1.z; phv[7]=p1.w;
#pragma unroll
            for (int q = 0; q < 7; q++) {
                float4 jv = jup4[b * 7 + q];
                J[q*4+0]=jv.x; J[q*4+1]=jv.y; J[q*4+2]=jv.z; J[q*4+3]=jv.w;
            }
        }
        float hc1[NQ], ch[NQ], sh[NQ];
#pragma unroll
        for (int k = 0; k < NQ; k++) {
            hc1[k] = fmaf(0.5f, phv[k], s_hw[k].x);
            __sincosf(0.5f * th[k], &sh[k], &ch[k]);
        }

        // Ising Walsh table over reg bits (lane part in index 0)
        float exr[8];
        {
            const float HP = 1.5707963267948966f;
            float sg[5];
#pragma unroll
            for (int k = 0; k < 5; k++)
                sg[k] = ((lane >> (4 - k)) & 1) ? 1.f : -1.f;
            float il = 0.f;
            {
                const int PI[10] = {0,0,0,0, 1,1,1, 2,2, 3};
                const int PJ[10] = {1,2,3,4, 2,3,4, 3,4, 4};
                const int PP[10] = {0,1,2,3, 7,8,9, 13,14, 18};
#pragma unroll
                for (int q = 0; q < 10; q++)
                    il = fmaf(-sg[PI[q]] * sg[PJ[q]], J[PP[q]], il);
            }
            float U0 = 0.f, U1 = 0.f, U2 = 0.f;
            {
                const int P5[5] = {4, 10, 15, 19, 22};
#pragma unroll
                for (int i = 0; i < 5; i++) {
                    U0 = fmaf(sg[i], J[P5[i]],     U0);
                    U1 = fmaf(sg[i], J[P5[i] + 1], U1);
                    U2 = fmaf(sg[i], J[P5[i] + 2], U2);
                }
            }
            float J56 = J[25], J57 = J[26], J67 = J[27];
            exr[0] = il * HP;  exr[1] = U2 * HP;   exr[2] = U1 * HP;  exr[3] = -J67 * HP;
            exr[4] = U0 * HP;  exr[5] = -J57 * HP; exr[6] = -J56 * HP; exr[7] = 0.f;
        }

        // product state after encoding RY + DIAG1 phase
        float base = 0.f;
#pragma unroll
        for (int k = 0; k < 5; k++)
            base += ((lane >> (4 - k)) & 1) ? hc1[k] : -hc1[k];
        float w0[8];
        w0[0] = base + exr[0];   w0[1] = exr[1] - hc1[7];
        w0[2] = exr[2] - hc1[6]; w0[3] = exr[3];
        w0[4] = exr[4] - hc1[5]; w0[5] = exr[5];
        w0[6] = exr[6];          w0[7] = exr[7];
#pragma unroll
        for (int st = 1; st < 8; st <<= 1) {
#pragma unroll
            for (int i = 0; i < 8; i++) {
                if (!(i & st)) {
                    float u = w0[i], v = w0[i | st];
                    w0[i] = u + v; w0[i | st] = u - v;
                }
            }
        }
        float lf = 1.f;
#pragma unroll
        for (int k = 0; k < 5; k++)
            lf *= ((lane >> (4 - k)) & 1) ? sh[k] : ch[k];
        float f56[4];
        f56[0] = ch[5] * ch[6]; f56[1] = ch[5] * sh[6];
        f56[2] = sh[5] * ch[6]; f56[3] = sh[5] * sh[6];
#pragma unroll
        for (int r = 0; r < 8; r++) {
            float v = lf * f56[r >> 1] * ((r & 1) ? sh[7] : ch[7]);
            float phr = w0[r];
            float q = rintf(phr * 0.15915494309189535f);
            phr = fmaf(q, -6.2831855f, phr);
            float cc, ss;
            __sincosf(phr, &ss, &cc);
            a[r] = pk(v * cc, v * ss);
        }
    }

    // ===== Round A: layer 0 Rot-RY =====
    {
        ry_lane_m(a, s_cs[0].x, s_cs[0].y, 16, (lane >> 4) & 1u);
        ry_lane_m(a, s_cs[1].x, s_cs[1].y,  8, (lane >> 3) & 1u);
        ry_lane_m(a, s_cs[2].x, s_cs[2].y,  4, (lane >> 2) & 1u);
        ry_lane_m(a, s_cs[3].x, s_cs[3].y,  2, (lane >> 1) & 1u);
        ry_lane_m(a, s_cs[4].x, s_cs[4].y,  1,  lane       & 1u);
        ry_reg_m(a, s_cs[5].x, s_cs[5].y, 4);
        ry_reg_m(a, s_cs[6].x, s_cs[6].y, 2);
        ry_reg_m(a, s_cs[7].x, s_cs[7].y, 1);
    }

    // ===== DIAG2 via block-shared complex table (conflict-free LDS.64) =====
#pragma unroll
    for (int r = 0; r < 8; r++) {
        u64 v = s_d2t[r][lane];
        float cc, ss, x, y;
        upk(v, cc, ss); upk(a[r], x, y);
        a[r] = pk(fmaf(cc, x, -ss * y), fmaf(cc, y, ss * x));
    }

    // ===== CNOT ring 1: lane part folded into relabeling =====
    const unsigned lam4 = (lane >> 4) & 1u;
    const unsigned lam3 = lam4 ^ ((lane >> 3) & 1u);
    const unsigned lam2 = lam3 ^ ((lane >> 2) & 1u);
    const unsigned lam1 = lam2 ^ ((lane >> 1) & 1u);
    const unsigned lam0 = lam1 ^ (lane & 1u);

    {
        const bool cs = lam0;
#pragma unroll
        for (int r = 0; r < 4; r++) {
            u64 t0 = a[r], t1 = a[r | 4];
            a[r]     = cs ? t1 : t0;
            a[r | 4] = cs ? t0 : t1;
        }
    }
    { u64 q = a[4]; a[4] = a[6]; a[6] = q; q = a[5]; a[5] = a[7]; a[7] = q; }
    { u64 q = a[2]; a[2] = a[3]; a[3] = q; q = a[6]; a[6] = a[7]; a[7] = q; }
    // (7,0) step [odd-r shfl 24] folded into Round B k=0 via operand swap.

    // ===== Round B: per-qubit U = RY(psi1) * RZ(2*hc3) * RY(theta/2-enc) =====
    // Batch angles reloaded here (L1-hot, warp-uniform) so nothing lived across Round A.
    {
        float th[NQ], phv[NQ];
        {
            float4 t0 = theta4[b * 2], t1 = theta4[b * 2 + 1];
            th[0]=t0.x; th[1]=t0.y; th[2]=t0.z; th[3]=t0.w;
            th[4]=t1.x; th[5]=t1.y; th[6]=t1.z; th[7]=t1.w;
            float4 p0 = phi4[b * 2], p1 = phi4[b * 2 + 1];
            phv[0]=p0.x; phv[1]=p0.y; phv[2]=p0.z; phv[3]=p0.w;
            phv[4]=p1.x; phv[5]=p1.y; phv[6]=p1.z; phv[7]=p1.w;
        }
        const int  MSK[5]  = { 24, 12, 6, 3, 1 };
        const unsigned LAMV[5] = { lam4, lam3, lam2, lam1, lam0 };
#pragma unroll
        for (int k = 0; k < NQ; k++) {
            float cqk, sqk;
            __sincosf(0.25f * th[k], &sqk, &cqk);
            float hc3 = fmaf(0.25f, phv[k], s_hw[k].y);   // 0.25*phi + 0.5*phi_w(l1)
            float cd, sd;
            __sincosf(hc3, &sd, &cd);
            float2 pw = s_cs[NQ + k];               // cos/sin(psi1/2)
            float t1 = pw.x * cqk, t2 = pw.y * sqk;
            float t3 = pw.x * sqk, t4 = pw.y * cqk;
            float P = t1 - t2, Q = t1 + t2, R = t3 + t4, S = t4 - t3;
            float cdP = cd * P, sdQ = sd * Q, cdR = cd * R, sdS = sd * S;
            if (k < 5) {
                const unsigned bb = LAMV[k];
                const float csy = bb ? sdQ : -sdQ;
                const float cpx = bb ? cdR : -cdR;
                const u64 A0 = bc2(cdP), A1 = pk(-csy, csy);
                const u64 B0 = bc2(cpx), B1 = pk(sdS, -sdS);
#pragma unroll
                for (int r = 0; r < 8; r++) {
                    u64 p = shflx2(a[r], MSK[k]);
                    // k==0 odd regs: ring-1 (7,0) fold -> swap operand roles
                    u64 xs = (k == 0 && (r & 1)) ? p : a[r];
                    u64 ys = (k == 0 && (r & 1)) ? a[r] : p;
                    a[r] = fma2(B1, sw2(ys),
                           fma2(B0, ys,
                           fma2(A1, sw2(xs), mul2(A0, xs))));
                }
            } else {
                const int m = 1 << (7 - k);
                const u64 C0 = bc2(cdP);
                const u64 Cl = pk(sdQ, -sdQ), Ch = pk(-sdQ, sdQ);
                const u64 D0n = bc2(-cdR), D0p = bc2(cdR);
                const u64 D1 = pk(sdS, -sdS);
#pragma unroll
                for (int r = 0; r < 8; r++) {
                    if (!(r & m)) {
                        u64 lo = a[r], hi = a[r | m];
                        u64 swl = sw2(lo), swh = sw2(hi);
                        a[r]     = fma2(D1, swh, fma2(D0n, hi,
                                   fma2(Cl, swl, mul2(C0, lo))));
                        a[r | m] = fma2(Ch, swh, fma2(C0, hi,
                                   fma2(D1, swl, mul2(D0p, lo))));
                    }
                }
            }
        }
    }

    // ===== expectations: <Z_k>_final = <chi_{M_k}>_pre-ring2 =====
    float pwv[8];
#pragma unroll
    for (int r = 0; r < 8; r++) {
        float x, y; upk(a[r], x, y);
        pwv[r] = fmaf(x, x, y * y);
    }
#pragma unroll
    for (int st = 1; st < 8; st <<= 1) {
#pragma unroll
        for (int i = 0; i < 8; i++) {
            if (!(i & st)) {
                float u = pwv[i], v = pwv[i | st];
                pwv[i] = u + v; pwv[i | st] = u - v;
            }
        }
    }
    float v0 = lane_wht(pwv[0], lane);
    float v2 = lane_wht(pwv[2], lane);
    float v4 = lane_wht(pwv[4], lane);
    float v5 = lane_wht(pwv[5], lane);

    float* ob = out + (size_t)b * NQ;
    if (lane == 3)  ob[0] = v2;
    if (lane == 30) ob[1] = v5;
    if (lane == 12) ob[2] = v0;
    if (lane == 6)  { ob[3] = v0; ob[5] = v4; ob[7] = v5; }
    if (lane == 19) { ob[4] = v0; ob[6] = v2; }
}

extern "C" void kernel_launch(void* const* d_in, const int* in_sizes, int n_in,
                              void* d_out, int out_size) {
    const float4* theta4 = (const float4*)d_in[0];
    const float4* phi4   = (const float4*)d_in[1];
    const float4* jup4   = (const float4*)d_in[2];
    const float*  w      = (const float*)d_in[3];
    float* out = (float*)d_out;

    const int grid = (NB * 32) / THREADS;
    vqc_kernel<<<grid, THREADS>>>(theta4, phi4, jup4, w, out);
}